// round 6
// baseline (speedup 1.0000x reference)
#include <cuda_runtime.h>
#include <cstdint>

// ============================================================================
// Problem dims (fixed by the dataset)
// ============================================================================
#define B_DIM 256
#define P_DIM 64
#define Q_DIM 128
#define C_DIM 1000
#define F_DIM 2048

// ============================================================================
// Config
// ============================================================================
static constexpr int THREADS    = 256;           // 8 warps: 2 (m) x 4 (n)
static constexpr int KT         = 32;            // k-elems (fp32) per stage
static constexpr int NSTAGES    = F_DIM / KT;    // 64
static constexpr int NBUF       = 3;             // cp.async pipeline depth
static constexpr int TILE_BYTES = 128 * KT * 4;  // 16384 (A or B tile)
static constexpr int STAGE_BYTES = 2 * TILE_BYTES;   // 32768

// smem layout (bytes). Tile triple-buffer [0, 98304) is reused as the logits
// matrix (128 x 129 fp32, padded stride to dodge bank conflicts) post-GEMM.
static constexpr int LOGIT_STRIDE = 129;
static constexpr int SM_LOGITS = 0;                        // 66048 bytes used
static constexpr int SM_BIAS   = NBUF * STAGE_BYTES;       // 98304: 128 f32
static constexpr int SM_LSE    = SM_BIAS + 512;            // 128 f32
static constexpr int SM_PMAX   = SM_LSE + 512;             // 256 f32
static constexpr int SM_PSUM   = SM_PMAX + 1024;           // 256 f32
static constexpr int SM_IDX    = SM_PSUM + 1024;           // 1000 i32 (4000 B)
static constexpr int SM_FLAG   = SM_IDX + 4000;            // 1 i32 (i64 flag)
static constexpr int SM_TOTAL  = SM_IDX + 4096;            // 105472

// ============================================================================
// Helpers
// ============================================================================
__device__ __forceinline__ uint32_t smem_to_u32(const void* smem_ptr) {
    uint32_t addr;
    asm("{ .reg .u64 tmp; cvta.to.shared.u64 tmp, %1; cvt.u32.u64 %0, tmp; }"
        : "=r"(addr) : "l"(smem_ptr));
    return addr;
}

__device__ __forceinline__ uint32_t f2tf32(float f) {
    uint32_t u;
    asm("cvt.rna.tf32.f32 %0, %1;" : "=r"(u) : "f"(f));
    return u;
}

__device__ __forceinline__ void mma_tf32(float* c, const uint32_t* a, const uint32_t* b) {
    asm volatile(
        "mma.sync.aligned.m16n8k8.row.col.f32.tf32.tf32.f32 "
        "{%0,%1,%2,%3}, {%4,%5,%6,%7}, {%8,%9}, {%0,%1,%2,%3};"
        : "+f"(c[0]), "+f"(c[1]), "+f"(c[2]), "+f"(c[3])
        : "r"(a[0]), "r"(a[1]), "r"(a[2]), "r"(a[3]), "r"(b[0]), "r"(b[1]));
}

#define CP_ASYNC_16(dst_u32, src_sz) \
    asm volatile("cp.async.cg.shared.global [%0], [%1], 16;" \
                 :: "r"(dst_u32), "l"(src_sz) : "memory")
#define CP_ASYNC_COMMIT() asm volatile("cp.async.commit_group;" ::: "memory")
#define CP_ASYNC_WAIT(n)  asm volatile("cp.async.wait_group %0;" :: "n"(n) : "memory")

// ============================================================================
// Fused kernel: tf32 mma.sync GEMM (128x128x2048) + bias + log_softmax + gather
//   grid = (2 m-tiles of 128 batch rows, 64 partitions)
// ============================================================================
__global__ void __launch_bounds__(THREADS, 1)
combinatorial_classifier_kernel(
    const float* __restrict__ x,            // [B, F]
    const float* __restrict__ W,            // [P*Q, F] (K contiguous)
    const float* __restrict__ bias,         // [P, Q]
    const void*  __restrict__ part_idx,     // [P, C] int32 OR int64 (detected)
    float* __restrict__ out)                // [B, P, C]
{
    extern __shared__ char smem[];
    const uint32_t su  = smem_to_u32(smem);
    const int tid      = threadIdx.x;
    const int wid      = tid >> 5;
    const int lid      = tid & 31;
    const int m_tile   = blockIdx.x;          // 0..1
    const int p        = blockIdx.y;          // 0..63
    const int warp_m   = wid >> 2;            // 0..1  -> 64 rows each
    const int warp_n   = wid & 3;             // 0..3  -> 32 cols each
    const int g        = lid >> 2;            // 0..7
    const int tg       = lid & 3;             // 0..3

    float* logits_s = reinterpret_cast<float*>(smem + SM_LOGITS);
    float* bias_s   = reinterpret_cast<float*>(smem + SM_BIAS);
    float* lse_s    = reinterpret_cast<float*>(smem + SM_LSE);
    float* pmax_s   = reinterpret_cast<float*>(smem + SM_PMAX);
    float* psum_s   = reinterpret_cast<float*>(smem + SM_PSUM);
    int*   idx_s    = reinterpret_cast<int*>(smem + SM_IDX);
    int*   flag_s   = reinterpret_cast<int*>(smem + SM_FLAG);

    const size_t xa = __cvta_generic_to_global(x + (size_t)(m_tile * 128) * F_DIM);
    const size_t wa = __cvta_generic_to_global(W + (size_t)(p * Q_DIM) * F_DIM);

    // ---- async tile loader: 128 rows x 32 f32, XOR-swizzled 16B chunks -----
    auto load_stage = [&](int s) {
        const uint32_t sb = su + (uint32_t)((s % NBUF) * STAGE_BYTES);
        const int kk = s * KT;
#pragma unroll
        for (int u = 0; u < 4; u++) {
            const int tcn = u * THREADS + tid;     // 0..1023 chunk id
            const int row = tcn >> 3;
            const int cc  = tcn & 7;
            const uint32_t dst = sb + (uint32_t)(row * 128 + ((cc ^ (row & 7)) << 4));
            const size_t byte_off = ((size_t)row * F_DIM + kk + cc * 4) * 4;
            CP_ASYNC_16(dst, xa + byte_off);                   // A (x)
            CP_ASYNC_16(dst + TILE_BYTES, wa + byte_off);      // B (W)
        }
        CP_ASYNC_COMMIT();
    };

    // Prefetch first two stages immediately (hide DRAM latency behind setup).
    load_stage(0);
    load_stage(1);

    // ---- detect part_idx dtype (int32 vs int64) ----------------------------
    // True int64 data with values in [0,128): every odd little-endian int32
    // word is 0. For int32 data, P(first 128 odd words all zero) = 128^-64.
    // Reads words [0, 256) of a buffer that holds >= 64000 int32 words under
    // either interpretation, so this never goes out of bounds.
    if (wid == 0) {
        const int* p32 = reinterpret_cast<const int*>(part_idx);
        int all0 = 1;
#pragma unroll
        for (int j = 0; j < 4; j++)
            all0 &= (p32[2 * (lid + j * 32) + 1] == 0);
        all0 = __all_sync(0xffffffffu, all0);
        if (lid == 0) *flag_s = all0;
    }
    // Stage bias (region disjoint from GEMM tiles).
    for (int i = tid; i < Q_DIM; i += THREADS)
        bias_s[i] = bias[p * Q_DIM + i];
    __syncthreads();

    // Stage gather indices with the detected stride; mask keeps smem in bounds.
    {
        const int is64 = *flag_s;
        if (is64) {
            const long long* p64 = reinterpret_cast<const long long*>(part_idx);
            for (int i = tid; i < C_DIM; i += THREADS)
                idx_s[i] = ((int)p64[(size_t)p * C_DIM + i]) & 127;
        } else {
            const int* p32 = reinterpret_cast<const int*>(part_idx);
            for (int i = tid; i < C_DIM; i += THREADS)
                idx_s[i] = p32[(size_t)p * C_DIM + i] & 127;
        }
    }

    float c[4][4][4];
#pragma unroll
    for (int mi = 0; mi < 4; mi++)
#pragma unroll
        for (int ni = 0; ni < 4; ni++)
#pragma unroll
            for (int j = 0; j < 4; j++) c[mi][ni][j] = 0.f;

    // ---- mainloop: 3-stage cp.async pipeline -------------------------------
#pragma unroll 1
    for (int s = 0; s < NSTAGES; s++) {
        // Issue prefetch for s+2 (buffer (s+2)%3, consumed at stage s-1 which
        // ended with __syncthreads), then drain stage s's group.
        if (s + 2 < NSTAGES) {
            load_stage(s + 2);
            CP_ASYNC_WAIT(2);
        } else if (s + 1 < NSTAGES) {
            CP_ASYNC_WAIT(1);
        } else {
            CP_ASYNC_WAIT(0);
        }
        __syncthreads();

        const float* As = reinterpret_cast<const float*>(smem + (s % NBUF) * STAGE_BYTES);
        const float* Bs = As + 128 * KT;

#pragma unroll
        for (int ks = 0; ks < 4; ks++) {
            uint32_t a[4][4], b[4][2];
#pragma unroll
            for (int mi = 0; mi < 4; mi++) {
                const int r0  = warp_m * 64 + mi * 16 + g;   // r0+8: same &7
                const int sw0 = (((2 * ks)     ^ (r0 & 7)) << 2) + tg;
                const int sw1 = (((2 * ks + 1) ^ (r0 & 7)) << 2) + tg;
                a[mi][0] = f2tf32(As[r0 * KT + sw0]);
                a[mi][1] = f2tf32(As[(r0 + 8) * KT + sw0]);
                a[mi][2] = f2tf32(As[r0 * KT + sw1]);
                a[mi][3] = f2tf32(As[(r0 + 8) * KT + sw1]);
            }
#pragma unroll
            for (int ni = 0; ni < 4; ni++) {
                const int n0  = warp_n * 32 + ni * 8 + g;
                const int sw0 = (((2 * ks)     ^ (n0 & 7)) << 2) + tg;
                const int sw1 = (((2 * ks + 1) ^ (n0 & 7)) << 2) + tg;
                b[ni][0] = f2tf32(Bs[n0 * KT + sw0]);
                b[ni][1] = f2tf32(Bs[n0 * KT + sw1]);
            }
#pragma unroll
            for (int mi = 0; mi < 4; mi++)
#pragma unroll
                for (int ni = 0; ni < 4; ni++)
                    mma_tf32(c[mi][ni], a[mi], b[ni]);
        }
        __syncthreads();   // protect buffer before the next prefetch overwrite
    }

    // ---- epilogue: logits -> smem (bias added) -----------------------------
#pragma unroll
    for (int mi = 0; mi < 4; mi++) {
        const int r0 = warp_m * 64 + mi * 16 + g;
#pragma unroll
        for (int ni = 0; ni < 4; ni++) {
            const int col = warp_n * 32 + ni * 8 + tg * 2;
            logits_s[r0 * LOGIT_STRIDE + col]           = c[mi][ni][0] + bias_s[col];
            logits_s[r0 * LOGIT_STRIDE + col + 1]       = c[mi][ni][1] + bias_s[col + 1];
            logits_s[(r0 + 8) * LOGIT_STRIDE + col]     = c[mi][ni][2] + bias_s[col];
            logits_s[(r0 + 8) * LOGIT_STRIDE + col + 1] = c[mi][ni][3] + bias_s[col + 1];
        }
    }
    __syncthreads();

    // ---- log_softmax: 2 threads per row (halves), then combine -------------
    {
        const int row = tid & 127;
        const int h   = tid >> 7;
        const float* lrow = logits_s + row * LOGIT_STRIDE + h * 64;
        float m = -1e30f;
#pragma unroll 8
        for (int j = 0; j < 64; j++) m = fmaxf(m, lrow[j]);
        pmax_s[tid] = m;
        __syncthreads();
        const float M = fmaxf(pmax_s[row], pmax_s[row + 128]);
        float ssum = 0.f;
#pragma unroll 8
        for (int j = 0; j < 64; j++) ssum += __expf(lrow[j] - M);
        psum_s[tid] = ssum;
        __syncthreads();
        if (tid < 128)
            lse_s[tid] = M + __logf(psum_s[tid] + psum_s[tid + 128]);
        __syncthreads();
    }

    // ---- gather: out[b, p, c] = logits[b, idx[p,c]] - lse[b] ---------------
    {
        const int total = 128 * C_DIM;
        for (int i = tid; i < total; i += THREADS) {
            const int r  = i / C_DIM;
            const int cc = i - r * C_DIM;
            const float val = logits_s[r * LOGIT_STRIDE + idx_s[cc]] - lse_s[r];
            out[((size_t)(m_tile * 128 + r) * P_DIM + p) * C_DIM + cc] = val;
        }
    }
}

// ============================================================================
// Launch — identify inputs by element count (robust to metadata ordering)
// ============================================================================
extern "C" void kernel_launch(void* const* d_in, const int* in_sizes, int n_in,
                              void* d_out, int out_size) {
    const float* x        = nullptr;   // 256*2048      = 524288
    const float* W        = nullptr;   // 64*128*2048   = 16777216
    const float* bias     = nullptr;   // 64*128        = 8192
    const void*  part_idx = nullptr;   // 64*1000       = 64000

    for (int i = 0; i < n_in; i++) {
        switch (in_sizes[i]) {
            case 524288:   x        = (const float*)d_in[i]; break;
            case 16777216: W        = (const float*)d_in[i]; break;
            case 8192:     bias     = (const float*)d_in[i]; break;
            case 64000:    part_idx = d_in[i];               break;
            default: break;
        }
    }
    // Fallback to positional order if any lookup failed.
    if (!x)        x        = (const float*)d_in[0];
    if (!W)        W        = (const float*)d_in[1];
    if (!bias)     bias     = (const float*)d_in[2];
    if (!part_idx) part_idx = d_in[3];

    float* out = (float*)d_out;

    cudaFuncSetAttribute(combinatorial_classifier_kernel,
                         cudaFuncAttributeMaxDynamicSharedMemorySize, SM_TOTAL);

    dim3 grid(2, P_DIM);
    combinatorial_classifier_kernel<<<grid, THREADS, SM_TOTAL>>>(x, W, bias, part_idx, out);
}